// round 1
// baseline (speedup 1.0000x reference)
#include <cuda_runtime.h>
#include <cuda_bf16.h>
#include <cstdint>

// Problem shape
#define N_BATCH 32
#define CH      64
#define HH      112
#define WW      112
#define NX      (N_BATCH*CH*HH*WW)   // 25,690,112
#define NWELEM  (64*64*3*3)          // 36,864

// Scratch: quantized tensors as bf16 (lossless: BFP8 values are k*2^(e-7), |k|<=256)
__device__ __nv_bfloat16 g_xq[NX];
__device__ __nv_bfloat16 g_wq[NWELEM];

// ---------------------------------------------------------------------------
// BFP quantize: one warp per group of 36 flattened elements.
// e = floor(log2(max|v|)); scale = 2^(e-7); q = rint(v/scale)*scale.
// exp2f(int) is exact, so v*exp2f(7-e) == v/scale bit-exactly; rintf is
// round-half-even, matching jnp.round.
// ---------------------------------------------------------------------------
__global__ void bfp_quant_kernel(const float* __restrict__ src, int n,
                                 __nv_bfloat16* __restrict__ dst) {
    const int lane   = threadIdx.x & 31;
    const int warp   = (blockIdx.x * blockDim.x + threadIdx.x) >> 5;
    const int nWarps = (gridDim.x * blockDim.x) >> 5;
    const int nGroups = (n + 35) / 36;

    for (int g = warp; g < nGroups; g += nWarps) {
        const int base = g * 36;
        const int i0 = base + lane;
        const int i1 = base + 32 + lane;
        const bool p0 = (i0 < n);
        const bool p1 = (lane < 4) && (i1 < n);
        float v0 = p0 ? src[i0] : 0.0f;
        float v1 = p1 ? src[i1] : 0.0f;

        float m = fmaxf(fabsf(v0), fabsf(v1));
        #pragma unroll
        for (int off = 16; off > 0; off >>= 1)
            m = fmaxf(m, __shfl_xor_sync(0xffffffffu, m, off));

        float q0 = 0.0f, q1 = 0.0f;
        if (m > 0.0f) {
            float e     = floorf(log2f(m));
            float scale = exp2f(e - 7.0f);
            float inv   = exp2f(7.0f - e);
            q0 = rintf(v0 * inv) * scale;
            q1 = rintf(v1 * inv) * scale;
        }
        if (p0) dst[i0] = __float2bfloat16(q0);
        if (p1) dst[i1] = __float2bfloat16(q1);
    }
}

// ---------------------------------------------------------------------------
// Direct conv 3x3, pad 1, NCHW. Per block: n fixed, all 64 co, 4h x 28w tile.
// Shared: full weights [ci*9+k][co] with padded stride; input tile
// [64ci][6h][30w] (stride 36 to spread banks).
// Thread (256/block): 4 co x 7 w x 1 h -> 28 fp32 accumulators.
// ---------------------------------------------------------------------------
#define TW 28
#define TH 4
#define SW_STRIDE 584                       // 576 + 8 pad (bank spread)
#define SX_STRIDE 36                        // 30 used + pad
#define SW_ELEMS  (64 * SW_STRIDE)          // 37,376 bf16
#define SX_ELEMS  (64 * 6 * SX_STRIDE)      // 13,824 bf16
#define SMEM_BYTES ((SW_ELEMS + SX_ELEMS) * 2)

__global__ __launch_bounds__(256, 2)
void conv_kernel(const __nv_bfloat16* __restrict__ xq,
                 const __nv_bfloat16* __restrict__ wq,
                 const float* __restrict__ bias,
                 float* __restrict__ out) {
    extern __shared__ __nv_bfloat16 smem[];
    __nv_bfloat16* sW = smem;               // [co][ci*9+k] stride SW_STRIDE
    __nv_bfloat16* sX = smem + SW_ELEMS;    // [ci][hh][ww]  stride SX_STRIDE

    const int tid = threadIdx.x;
    const int n   = blockIdx.z;
    const int h0  = blockIdx.y * TH;
    const int w0  = blockIdx.x * TW;

    // Load weights: global [co][ci][kh][kw] coalesced -> sW[co*584 + (ci*9+k)]
    for (int idx = tid; idx < NWELEM; idx += 256) {
        int co = idx / 576;
        int r  = idx - co * 576;
        sW[co * SW_STRIDE + r] = wq[idx];
    }

    // Load input tile: rows h0-1..h0+4, cols w0-1..w0+28, zero-padded OOB
    for (int idx = tid; idx < 64 * 6 * 30; idx += 256) {
        int ci = idx / 180;
        int r  = idx - ci * 180;
        int hh = r / 30;
        int ww = r - hh * 30;
        int h = h0 + hh - 1;
        int w = w0 + ww - 1;
        __nv_bfloat16 v = __float2bfloat16(0.0f);
        if (h >= 0 && h < HH && w >= 0 && w < WW)
            v = xq[((n * CH + ci) * HH + h) * WW + w];
        sX[(ci * 6 + hh) * SX_STRIDE + ww] = v;
    }
    __syncthreads();

    const int w_grp   = tid & 3;            // 4 groups of 7 w
    const int h_idx   = (tid >> 2) & 3;     // 4 h rows
    const int co_base = (tid >> 4) * 4;     // 16 groups of 4 co

    float acc[4][7];
    #pragma unroll
    for (int i = 0; i < 4; ++i)
        #pragma unroll
        for (int j = 0; j < 7; ++j) acc[i][j] = 0.0f;

    const __nv_bfloat16* wbase = sW + co_base * SW_STRIDE;

    for (int ci = 0; ci < 64; ++ci) {
        #pragma unroll
        for (int kh = 0; kh < 3; ++kh) {
            const __nv_bfloat16* xrow =
                sX + (ci * 6 + h_idx + kh) * SX_STRIDE + w_grp * 7;
            float xv[9];
            #pragma unroll
            for (int j = 0; j < 9; ++j) xv[j] = __bfloat162float(xrow[j]);

            const int kbase = ci * 9 + kh * 3;
            #pragma unroll
            for (int kw = 0; kw < 3; ++kw) {
                #pragma unroll
                for (int i = 0; i < 4; ++i) {
                    float wv = __bfloat162float(wbase[i * SW_STRIDE + kbase + kw]);
                    #pragma unroll
                    for (int j = 0; j < 7; ++j)
                        acc[i][j] = fmaf(wv, xv[j + kw], acc[i][j]);
                }
            }
        }
    }

    // Epilogue
    const int h = h0 + h_idx;
    const int wbeg = w0 + w_grp * 7;
    #pragma unroll
    for (int i = 0; i < 4; ++i) {
        const int co = co_base + i;
        const float b = bias[co];
        float* orow = out + ((n * CH + co) * HH + h) * WW + wbeg;
        #pragma unroll
        for (int j = 0; j < 7; ++j)
            orow[j] = acc[i][j] + b;
    }
}

// ---------------------------------------------------------------------------
extern "C" void kernel_launch(void* const* d_in, const int* in_sizes, int n_in,
                              void* d_out, int out_size) {
    const float* x    = (const float*)d_in[0];
    const float* w    = (const float*)d_in[1];
    const float* bias = (const float*)d_in[2];
    float* out        = (float*)d_out;

    void *pxq = nullptr, *pwq = nullptr;
    cudaGetSymbolAddress(&pxq, g_xq);
    cudaGetSymbolAddress(&pwq, g_wq);
    __nv_bfloat16* xq = (__nv_bfloat16*)pxq;
    __nv_bfloat16* wq = (__nv_bfloat16*)pwq;

    bfp_quant_kernel<<<2048, 256>>>(x, NX, xq);
    bfp_quant_kernel<<<32, 256>>>(w, NWELEM, wq);

    cudaFuncSetAttribute(conv_kernel,
                         cudaFuncAttributeMaxDynamicSharedMemorySize,
                         SMEM_BYTES);
    conv_kernel<<<dim3(WW / TW, HH / TH, N_BATCH), 256, SMEM_BYTES>>>(
        xq, wq, bias, out);
}

// round 3
// speedup vs baseline: 3.2933x; 3.2933x over previous
#include <cuda_runtime.h>
#include <cuda_bf16.h>
#include <cstdint>

// ---------------------------------------------------------------------------
// Problem shape
// ---------------------------------------------------------------------------
#define N_BATCH 32
#define CH      64
#define HH      112
#define WW      112
#define PIX     (HH*WW)              // 12544 pixels per image
#define NX      (N_BATCH*CH*PIX)     // 25,690,112
#define NWELEM  (64*64*3*3)          // 36,864
#define TILES_PER_IMG (PIX/128)      // 98
#define NTILES  (N_BATCH*TILES_PER_IMG)  // 3136

// Scratch (device globals; no runtime allocation allowed)
__device__ __nv_bfloat16 g_xq[NX];       // quantized x, NCHW bf16
__device__ __nv_bfloat16 g_xt[NX];       // quantized x, NHWC bf16
__device__ __nv_bfloat16 g_wq[NWELEM];   // quantized w, OIHW bf16
__device__ __nv_bfloat16 g_wk[9*64*64];  // repacked:  [k][co][ci] bf16

#define SW128(off) ((off) ^ (((off) >> 3) & 0x70))

// ---------------------------------------------------------------------------
// BFP quantize (exact vs reference; verified rel_err == 0.0 in round 1)
// ---------------------------------------------------------------------------
__global__ void bfp_quant_kernel(const float* __restrict__ src, int n,
                                 __nv_bfloat16* __restrict__ dst) {
    const int lane   = threadIdx.x & 31;
    const int warp   = (blockIdx.x * blockDim.x + threadIdx.x) >> 5;
    const int nWarps = (gridDim.x * blockDim.x) >> 5;
    const int nGroups = (n + 35) / 36;

    for (int g = warp; g < nGroups; g += nWarps) {
        const int base = g * 36;
        const int i0 = base + lane;
        const int i1 = base + 32 + lane;
        const bool p0 = (i0 < n);
        const bool p1 = (lane < 4) && (i1 < n);
        float v0 = p0 ? src[i0] : 0.0f;
        float v1 = p1 ? src[i1] : 0.0f;

        float m = fmaxf(fabsf(v0), fabsf(v1));
        #pragma unroll
        for (int off = 16; off > 0; off >>= 1)
            m = fmaxf(m, __shfl_xor_sync(0xffffffffu, m, off));

        float q0 = 0.0f, q1 = 0.0f;
        if (m > 0.0f) {
            float e     = floorf(log2f(m));
            float scale = exp2f(e - 7.0f);
            float inv   = exp2f(7.0f - e);
            q0 = rintf(v0 * inv) * scale;
            q1 = rintf(v1 * inv) * scale;
        }
        if (p0) dst[i0] = __float2bfloat16(q0);
        if (p1) dst[i1] = __float2bfloat16(q1);
    }
}

// ---------------------------------------------------------------------------
// NCHW bf16 -> NHWC bf16 transpose (64 ci x 64 pixels per block, smem-staged)
// ---------------------------------------------------------------------------
__global__ __launch_bounds__(256)
void transpose_kernel(const __nv_bfloat16* __restrict__ src,
                      __nv_bfloat16* __restrict__ dst) {
    __shared__ __nv_bfloat16 s[64 * 65];
    const int tid = threadIdx.x;
    const int n   = blockIdx.y;
    const int p0  = blockIdx.x * 64;

    #pragma unroll
    for (int it = 0; it < 2; ++it) {
        int idx = tid + it * 256;          // [0,512)
        int ci = idx >> 3, c = idx & 7;
        uint4 v = *(const uint4*)(src + ((n * 64 + ci) * PIX + p0) + c * 8);
        const __nv_bfloat16* e = (const __nv_bfloat16*)&v;
        #pragma unroll
        for (int j = 0; j < 8; ++j) s[ci * 65 + c * 8 + j] = e[j];
    }
    __syncthreads();
    #pragma unroll
    for (int it = 0; it < 2; ++it) {
        int idx = tid + it * 256;
        int pix = idx >> 3, c = idx & 7;
        uint4 v;
        __nv_bfloat16* e = (__nv_bfloat16*)&v;
        #pragma unroll
        for (int j = 0; j < 8; ++j) e[j] = s[(c * 8 + j) * 65 + pix];
        *(uint4*)(dst + ((size_t)(n * PIX + p0 + pix)) * 64 + c * 8) = v;
    }
}

// ---------------------------------------------------------------------------
// Weight repack: OIHW bf16 -> [k=kh*3+kw][co][ci] bf16
// ---------------------------------------------------------------------------
__global__ void repack_w_kernel(const __nv_bfloat16* __restrict__ wq,
                                __nv_bfloat16* __restrict__ wk) {
    int gid = blockIdx.x * 256 + threadIdx.x;
    if (gid >= 9 * 64 * 64) return;
    int k  = gid >> 12;
    int r  = gid & 4095;
    int co = r >> 6;
    int ci = r & 63;
    wk[gid] = wq[co * 576 + ci * 9 + k];
}

// ---------------------------------------------------------------------------
// mma.sync helpers
// ---------------------------------------------------------------------------
__device__ __forceinline__ void ldsm_x4(uint32_t& r0, uint32_t& r1,
                                        uint32_t& r2, uint32_t& r3,
                                        uint32_t addr) {
    asm volatile("ldmatrix.sync.aligned.m8n8.x4.shared.b16 {%0,%1,%2,%3}, [%4];"
                 : "=r"(r0), "=r"(r1), "=r"(r2), "=r"(r3) : "r"(addr));
}

__device__ __forceinline__ void mma_bf16(float* c, const uint32_t* a,
                                         uint32_t b0, uint32_t b1) {
    asm volatile(
        "mma.sync.aligned.m16n8k16.row.col.f32.bf16.bf16.f32 "
        "{%0,%1,%2,%3}, {%4,%5,%6,%7}, {%8,%9}, {%0,%1,%2,%3};"
        : "+f"(c[0]), "+f"(c[1]), "+f"(c[2]), "+f"(c[3])
        : "r"(a[0]), "r"(a[1]), "r"(a[2]), "r"(a[3]), "r"(b0), "r"(b1));
}

__device__ __forceinline__ uint32_t smem_u32(const void* p) {
    uint32_t a;
    asm("{ .reg .u64 t; cvta.to.shared.u64 t, %1; cvt.u32.u64 %0, t; }"
        : "=r"(a) : "l"(p));
    return a;
}

// ---------------------------------------------------------------------------
// Implicit-GEMM conv with HMMA (mma.sync), 512 threads / block.
// Tile: 128 flattened pixels (one image) x 64 co.
// D[128pix,64co] = sum over 9 taps: A_k[128pix,64ci] @ W_k[64co,64ci]^T
// Warp tile 32(m) x 16(n): wm = wid&3, wn = wid>>2.
// SMEM: B 9x8192 (SW128) | A 9x16384 (SW128) | bias 256B. Epilogue reuses A.
// ---------------------------------------------------------------------------
#define SMEM_B_OFF   0u
#define SMEM_A_OFF   73728u
#define SMEM_BIAS    (SMEM_A_OFF + 147456u)        // 221184
#define SMEM_TOTAL   (SMEM_BIAS + 256u)            // 221440 bytes
#define SOUT_STRIDE  132                            // floats, pads banks

__global__ __launch_bounds__(512, 1)
void conv_mma_kernel(const __nv_bfloat16* __restrict__ xt,
                     const __nv_bfloat16* __restrict__ wk,
                     const float* __restrict__ bias,
                     float* __restrict__ out) {
    extern __shared__ char smem[];
    const uint32_t sb = smem_u32(smem);
    float* sOut  = (float*)(smem + SMEM_A_OFF);     // reused after MMA
    float* sBias = (float*)(smem + SMEM_BIAS);

    const int tid  = threadIdx.x;
    const int wid  = tid >> 5;
    const int lane = tid & 31;
    const int wm   = wid & 3;        // m quadrant: pixels 32*wm..+31
    const int wn   = wid >> 2;       // n quadrant: co 16*wn..+15
    const int g    = lane >> 2;      // acc row within frag
    const int tg   = lane & 3;       // acc col pair within frag

    if (tid < 64) sBias[tid] = bias[tid];

    // Stage all 9 weight tiles once (SW128 K-major: row=co, 128B of ci)
    for (int idx = tid; idx < 9 * 64 * 8; idx += 512) {
        int c  = idx & 7;
        int co = (idx >> 3) & 63;
        int k  = idx >> 9;
        uint4 v = *(const uint4*)(wk + ((k * 64 + co) * 64) + c * 8);
        uint32_t off = (uint32_t)(co * 128 + c * 16);
        *(uint4*)(smem + SMEM_B_OFF + k * 8192 + SW128(off)) = v;
    }
    __syncthreads();

    // ldmatrix per-lane offsets (row = lane%16, col-half = lane/16)
    const int lrow = lane & 15;
    const int lcol = (lane >> 4) << 4;   // 0 or 16 bytes

    for (int t = blockIdx.x; t < NTILES; t += gridDim.x) {
        const int n  = t / TILES_PER_IMG;
        const int p0 = (t - n * TILES_PER_IMG) * 128;

        // Stage 9 shifted A tiles: row i = pixel p0+i, 128B = 64 ci
        for (int idx = tid; idx < 9 * 128 * 8; idx += 512) {
            int c = idx & 7;
            int i = (idx >> 3) & 127;
            int k = idx >> 10;
            int dh = k / 3 - 1, dw = k % 3 - 1;
            int p  = p0 + i;
            int oh = p / WW;
            int ow = p - oh * WW;
            int ih = oh + dh, iw = ow + dw;
            uint4 v = make_uint4(0u, 0u, 0u, 0u);
            if ((unsigned)ih < (unsigned)HH && (unsigned)iw < (unsigned)WW)
                v = *(const uint4*)(xt + ((size_t)n * PIX + ih * WW + iw) * 64 + c * 8);
            uint32_t off = (uint32_t)(i * 128 + c * 16);
            *(uint4*)(smem + SMEM_A_OFF + k * 16384 + SW128(off)) = v;
        }
        __syncthreads();

        float acc[2][2][4];
        #pragma unroll
        for (int mf = 0; mf < 2; ++mf)
            #pragma unroll
            for (int nf = 0; nf < 2; ++nf)
                #pragma unroll
                for (int j = 0; j < 4; ++j) acc[mf][nf][j] = 0.0f;

        for (int k = 0; k < 9; ++k) {
            const uint32_t aB = sb + SMEM_A_OFF + k * 16384;
            const uint32_t bB = sb + SMEM_B_OFF + k * 8192;
            #pragma unroll
            for (int s = 0; s < 4; ++s) {
                const int cb = s * 32;   // byte col for ci chunk of 16

                // B frag: 16 co x 16 ci
                uint32_t b0, b1, b2, b3;
                {
                    uint32_t off = (uint32_t)((wn * 16 + lrow) * 128 + cb + lcol);
                    ldsm_x4(b0, b1, b2, b3, bB + SW128(off));
                }
                // A frags: two m16 x k16
                uint32_t a[2][4];
                #pragma unroll
                for (int mf = 0; mf < 2; ++mf) {
                    uint32_t off = (uint32_t)((wm * 32 + mf * 16 + lrow) * 128 + cb + lcol);
                    ldsm_x4(a[mf][0], a[mf][1], a[mf][2], a[mf][3], aB + SW128(off));
                }
                #pragma unroll
                for (int mf = 0; mf < 2; ++mf) {
                    mma_bf16(acc[mf][0], a[mf], b0, b2);   // co wn*16+0..7
                    mma_bf16(acc[mf][1], a[mf], b1, b3);   // co wn*16+8..15
                }
            }
        }
        __syncthreads();   // all A reads done; safe to reuse A region

        // Write accumulators to sOut[co][pix] (padded stride, conflict-free)
        #pragma unroll
        for (int mf = 0; mf < 2; ++mf) {
            const int pixr = wm * 32 + mf * 16 + g;
            #pragma unroll
            for (int nf = 0; nf < 2; ++nf) {
                const int cob = wn * 16 + nf * 8 + tg * 2;
                sOut[cob * SOUT_STRIDE + pixr]           = acc[mf][nf][0];
                sOut[(cob + 1) * SOUT_STRIDE + pixr]     = acc[mf][nf][1];
                sOut[cob * SOUT_STRIDE + pixr + 8]       = acc[mf][nf][2];
                sOut[(cob + 1) * SOUT_STRIDE + pixr + 8] = acc[mf][nf][3];
            }
        }
        __syncthreads();

        // Coalesced NCHW store (+bias): 128 contiguous floats per co row
        #pragma unroll
        for (int it = 0; it < 16; ++it) {
            int idx = it * 512 + tid;
            int co  = idx >> 7;
            int pix = idx & 127;
            out[((size_t)n * 64 + co) * PIX + p0 + pix] =
                sOut[co * SOUT_STRIDE + pix] + sBias[co];
        }
        __syncthreads();   // before next tile overwrites sOut/A
    }
}

// ---------------------------------------------------------------------------
extern "C" void kernel_launch(void* const* d_in, const int* in_sizes, int n_in,
                              void* d_out, int out_size) {
    const float* x    = (const float*)d_in[0];
    const float* w    = (const float*)d_in[1];
    const float* bias = (const float*)d_in[2];
    float* out        = (float*)d_out;

    void *pxq, *pxt, *pwq, *pwk;
    cudaGetSymbolAddress(&pxq, g_xq);
    cudaGetSymbolAddress(&pxt, g_xt);
    cudaGetSymbolAddress(&pwq, g_wq);
    cudaGetSymbolAddress(&pwk, g_wk);
    __nv_bfloat16* xq = (__nv_bfloat16*)pxq;
    __nv_bfloat16* xt = (__nv_bfloat16*)pxt;
    __nv_bfloat16* wq = (__nv_bfloat16*)pwq;
    __nv_bfloat16* wk = (__nv_bfloat16*)pwk;

    bfp_quant_kernel<<<2048, 256>>>(x, NX, xq);
    bfp_quant_kernel<<<32, 256>>>(w, NWELEM, wq);
    transpose_kernel<<<dim3(PIX / 64, N_BATCH), 256>>>(xq, xt);
    repack_w_kernel<<<(9 * 64 * 64 + 255) / 256, 256>>>(wq, wk);

    cudaFuncSetAttribute(conv_mma_kernel,
                         cudaFuncAttributeMaxDynamicSharedMemorySize,
                         SMEM_TOTAL);
    conv_mma_kernel<<<148, 512, SMEM_TOTAL>>>(xt, wk, bias, out);
}

// round 5
// speedup vs baseline: 5.8292x; 1.7700x over previous
#include <cuda_runtime.h>
#include <cuda_bf16.h>
#include <cstdint>

// ---------------------------------------------------------------------------
// Problem shape
// ---------------------------------------------------------------------------
#define N_BATCH 32
#define CH      64
#define HH      112
#define WW      112
#define PIX     (HH*WW)              // 12544
#define NX      (N_BATCH*CH*PIX)     // 25,690,112
#define NWELEM  (64*64*3*3)          // 36,864
#define TILES_PER_IMG (PIX/128)      // 98
#define NTILES  (N_BATCH*TILES_PER_IMG)  // 3136

__device__ __align__(16) __nv_bfloat16 g_xq[NX];       // quantized x, NCHW
__device__ __align__(16) __nv_bfloat16 g_xt[NX];       // quantized x, NHWC
__device__ __align__(16) __nv_bfloat16 g_wq[NWELEM];   // quantized w, OIHW
__device__ __align__(16) __nv_bfloat16 g_wk[9*64*64];  // [k][co][ci]

#define SW128(off) ((off) ^ (((off) >> 3) & 0x70))

// ---------------------------------------------------------------------------
// BFP quantize, block-staged: 256 threads own 9216 elems = 256 groups of 36.
// Each thread: 9 float4 (one float4 never crosses a group since 4 | 36).
// ---------------------------------------------------------------------------
__global__ __launch_bounds__(256)
void bfp_quant_kernel(const float4* __restrict__ src, int n4,
                      uint2* __restrict__ dst) {
    __shared__ float sMax[2304];
    __shared__ float sScl[256];
    __shared__ float sInv[256];
    const int tid = threadIdx.x;
    const long base = (long)blockIdx.x * 2304;

    float4 v[9];
    #pragma unroll
    for (int r = 0; r < 9; ++r) {
        long j = base + r * 256 + tid;
        float4 x = make_float4(0.f, 0.f, 0.f, 0.f);
        if (j < n4) x = src[j];
        v[r] = x;
        sMax[r * 256 + tid] =
            fmaxf(fmaxf(fabsf(x.x), fabsf(x.y)), fmaxf(fabsf(x.z), fabsf(x.w)));
    }
    __syncthreads();
    {
        float m = sMax[tid * 9];
        #pragma unroll
        for (int i = 1; i < 9; ++i) m = fmaxf(m, sMax[tid * 9 + i]);
        float scl = 0.f, inv = 0.f;
        if (m > 0.f) {
            float e = floorf(log2f(m));
            scl = exp2f(e - 7.f);    // exact powers of two
            inv = exp2f(7.f - e);
        }
        sScl[tid] = scl;
        sInv[tid] = inv;
    }
    __syncthreads();
    #pragma unroll
    for (int r = 0; r < 9; ++r) {
        long j = base + r * 256 + tid;
        if (j >= n4) continue;
        int g = (r * 256 + tid) / 9;
        float scl = sScl[g], inv = sInv[g];
        float4 x = v[r];
        __nv_bfloat162 lo = __floats2bfloat162_rn(rintf(x.x * inv) * scl,
                                                  rintf(x.y * inv) * scl);
        __nv_bfloat162 hi = __floats2bfloat162_rn(rintf(x.z * inv) * scl,
                                                  rintf(x.w * inv) * scl);
        uint2 o;
        o.x = *(uint32_t*)&lo;
        o.y = *(uint32_t*)&hi;
        dst[j] = o;
    }
}

// ---------------------------------------------------------------------------
// NCHW bf16 -> NHWC bf16 transpose (64 ci x 64 pixels per block, smem-staged)
// ---------------------------------------------------------------------------
__global__ __launch_bounds__(256)
void transpose_kernel(const __nv_bfloat16* __restrict__ src,
                      __nv_bfloat16* __restrict__ dst) {
    __shared__ __nv_bfloat16 s[64 * 65];
    const int tid = threadIdx.x;
    const int n   = blockIdx.y;
    const int p0  = blockIdx.x * 64;

    #pragma unroll
    for (int it = 0; it < 2; ++it) {
        int idx = tid + it * 256;
        int ci = idx >> 3, c = idx & 7;
        uint4 v = *(const uint4*)(src + ((n * 64 + ci) * PIX + p0) + c * 8);
        const __nv_bfloat16* e = (const __nv_bfloat16*)&v;
        #pragma unroll
        for (int j = 0; j < 8; ++j) s[ci * 65 + c * 8 + j] = e[j];
    }
    __syncthreads();
    #pragma unroll
    for (int it = 0; it < 2; ++it) {
        int idx = tid + it * 256;
        int pix = idx >> 3, c = idx & 7;
        uint4 v;
        __nv_bfloat16* e = (__nv_bfloat16*)&v;
        #pragma unroll
        for (int j = 0; j < 8; ++j) e[j] = s[(c * 8 + j) * 65 + pix];
        *(uint4*)(dst + ((size_t)(n * PIX + p0 + pix)) * 64 + c * 8) = v;
    }
}

// ---------------------------------------------------------------------------
// Weight repack: OIHW bf16 -> [k][co][ci]
// ---------------------------------------------------------------------------
__global__ void repack_w_kernel(const __nv_bfloat16* __restrict__ wq,
                                __nv_bfloat16* __restrict__ wk) {
    int gid = blockIdx.x * 256 + threadIdx.x;
    if (gid >= 9 * 64 * 64) return;
    int k  = gid >> 12;
    int r  = gid & 4095;
    int co = r >> 6;
    int ci = r & 63;
    wk[gid] = wq[co * 576 + ci * 9 + k];
}

// ---------------------------------------------------------------------------
// mma.sync / cp.async helpers
// ---------------------------------------------------------------------------
__device__ __forceinline__ void ldsm_x4(uint32_t& r0, uint32_t& r1,
                                        uint32_t& r2, uint32_t& r3,
                                        uint32_t addr) {
    asm volatile("ldmatrix.sync.aligned.m8n8.x4.shared.b16 {%0,%1,%2,%3}, [%4];"
                 : "=r"(r0), "=r"(r1), "=r"(r2), "=r"(r3) : "r"(addr));
}
__device__ __forceinline__ void mma_bf16(float* c, const uint32_t* a,
                                         uint32_t b0, uint32_t b1) {
    asm volatile(
        "mma.sync.aligned.m16n8k16.row.col.f32.bf16.bf16.f32 "
        "{%0,%1,%2,%3}, {%4,%5,%6,%7}, {%8,%9}, {%0,%1,%2,%3};"
        : "+f"(c[0]), "+f"(c[1]), "+f"(c[2]), "+f"(c[3])
        : "r"(a[0]), "r"(a[1]), "r"(a[2]), "r"(a[3]), "r"(b0), "r"(b1));
}
__device__ __forceinline__ uint32_t smem_u32(const void* p) {
    uint32_t a;
    asm("{ .reg .u64 t; cvta.to.shared.u64 t, %1; cvt.u32.u64 %0, t; }"
        : "=r"(a) : "l"(p));
    return a;
}
__device__ __forceinline__ void cp_async16(uint32_t dst, const void* src, bool pred) {
    int sz = pred ? 16 : 0;
    asm volatile("cp.async.cg.shared.global [%0], [%1], 16, %2;"
                 :: "r"(dst), "l"(src), "r"(sz) : "memory");
}
#define CP_COMMIT() asm volatile("cp.async.commit_group;" ::: "memory")
#define CP_WAIT(N)  asm volatile("cp.async.wait_group %0;" :: "n"(N) : "memory")

// ---------------------------------------------------------------------------
// Conv: halo-layout implicit GEMM, cp.async double-buffered.
// Tile = 128 flat output pixels x 64 co.  A smem: [5 ih rows][114 w][64 ci]
// (w slots 0/113 zero = padding; OOB ih rows zero). Tap (dh,dw) = row offset
// dh*114+dw on per-lane ldmatrix addresses.
// SMEM: B 9x8192 | A0 73728 | A1 73728  -> 221184 bytes.
// ---------------------------------------------------------------------------
#define SMEM_B    0u
#define SMEM_A0   73728u
#define SMEM_A1   147456u
#define CONV_SMEM 221184u
#define A_STAGE_OPS 4560            // 5*114*8 x 16B

__global__ __launch_bounds__(512, 1)
void conv_mma_kernel(const __nv_bfloat16* __restrict__ xt,
                     const __nv_bfloat16* __restrict__ wk,
                     const float* __restrict__ bias,
                     float* __restrict__ out) {
    extern __shared__ char smem[];
    const uint32_t sb = smem_u32(smem);

    const int tid  = threadIdx.x;
    const int wid  = tid >> 5;
    const int lane = tid & 31;
    const int wm   = wid & 3;          // pixels 32*wm..+31
    const int wn   = wid >> 2;         // co 16*wn..+15
    const int lrow = lane & 15;
    const int lcol = (lane >> 4) << 4; // 0 or 16 bytes
    const int g8   = lane >> 2;
    const int tg   = lane & 3;

    // Per-thread bias values for the 4 co columns this thread owns
    float bv[2][2];
    #pragma unroll
    for (int nf = 0; nf < 2; ++nf) {
        int cob = wn * 16 + nf * 8 + tg * 2;
        bv[nf][0] = bias[cob];
        bv[nf][1] = bias[cob + 1];
    }

    // Stage all 9 weight tiles (SW128 K-major: row=co, 128B of ci)
    for (int idx = tid; idx < 9 * 64 * 8; idx += 512) {
        int c  = idx & 7;
        int co = (idx >> 3) & 63;
        int k  = idx >> 9;
        uint4 v = *(const uint4*)(wk + ((k * 64 + co) * 64) + c * 8);
        *(uint4*)(smem + SMEM_B + k * 8192 + SW128((uint32_t)(co * 128 + c * 16))) = v;
    }

    // Stage one tile's input rows into buffer at aoff via cp.async (zfill OOB)
    auto stage = [&](int t, uint32_t aoff) {
        const int n  = t / TILES_PER_IMG;
        const int p0 = (t - n * TILES_PER_IMG) * 128;
        const int hbase = p0 / WW - 1;
        const __nv_bfloat16* img = xt + (size_t)n * PIX * 64;
        #pragma unroll
        for (int it = 0; it < 9; ++it) {
            int idx = it * 512 + tid;
            if (idx < A_STAGE_OPS) {
                int c    = idx & 7;
                int rest = idx >> 3;           // 0..569
                int r    = rest / 114;
                int ws   = rest - r * 114;
                int ih   = hbase + r;
                int iw   = ws - 1;
                bool ok = ((unsigned)ih < (unsigned)HH) &
                          ((unsigned)iw < (unsigned)WW);
                const void* src = ok ? (const void*)(img + ((size_t)ih * WW + iw) * 64 + c * 8)
                                     : (const void*)img;
                cp_async16(sb + aoff + SW128((uint32_t)(rest * 128 + c * 16)), src, ok);
            }
        }
        CP_COMMIT();
    };

    int t = blockIdx.x;
    if (t < NTILES) stage(t, SMEM_A0);
    int pb = 0;

    for (; t < NTILES; t += gridDim.x, pb ^= 1) {
        const int n  = t / TILES_PER_IMG;
        const int p0 = (t - n * TILES_PER_IMG) * 128;
        const int oh0 = p0 / WW;
        const uint32_t ab = sb + (pb ? SMEM_A1 : SMEM_A0);

        const int tn = t + gridDim.x;
        if (tn < NTILES) {
            stage(tn, pb ? SMEM_A0 : SMEM_A1);
            CP_WAIT(1);
        } else {
            CP_WAIT(0);
        }
        __syncthreads();   // tile t data + (first iter) B visible to all

        // Per-lane base rows in halo layout for the two m-fragments
        int browA[2];
        #pragma unroll
        for (int mf = 0; mf < 2; ++mf) {
            int p  = p0 + wm * 32 + mf * 16 + lrow;
            int oh = p / WW;
            int ow = p - oh * WW;
            browA[mf] = (oh - oh0 + 1) * 114 + ow + 1;
        }

        float acc[2][2][4];
        #pragma unroll
        for (int mf = 0; mf < 2; ++mf)
            #pragma unroll
            for (int nf = 0; nf < 2; ++nf)
                #pragma unroll
                for (int j = 0; j < 4; ++j) acc[mf][nf][j] = 0.f;

        #pragma unroll
        for (int kh = 0; kh < 3; ++kh) {
            #pragma unroll
            for (int kw = 0; kw < 3; ++kw) {
                const int k = kh * 3 + kw;
                const int shift = (kh - 1) * 114 + (kw - 1);
                #pragma unroll
                for (int s = 0; s < 4; ++s) {
                    const int cb = s * 32;
                    uint32_t b0, b1, b2, b3;
                    ldsm_x4(b0, b1, b2, b3,
                            sb + SMEM_B + (uint32_t)k * 8192 +
                            SW128((uint32_t)((wn * 16 + lrow) * 128 + cb + lcol)));
                    uint32_t a[2][4];
                    #pragma unroll
                    for (int mf = 0; mf < 2; ++mf) {
                        int row = browA[mf] + shift;
                        ldsm_x4(a[mf][0], a[mf][1], a[mf][2], a[mf][3],
                                ab + SW128((uint32_t)(row * 128 + cb + lcol)));
                    }
                    #pragma unroll
                    for (int mf = 0; mf < 2; ++mf) {
                        mma_bf16(acc[mf][0], a[mf], b0, b2);
                        mma_bf16(acc[mf][1], a[mf], b1, b3);
                    }
                }
            }
        }
        __syncthreads();   // all ldmatrix reads of buf pb done before restage

        // Epilogue: direct 32B-sector stores, no smem
        float* outN = out + (size_t)n * 64 * PIX + p0;
        #pragma unroll
        for (int mf = 0; mf < 2; ++mf) {
            const int pix = wm * 32 + mf * 16 + g8;
            #pragma unroll
            for (int nf = 0; nf < 2; ++nf) {
                const int cob = wn * 16 + nf * 8 + tg * 2;
                float* r0 = outN + (size_t)cob * PIX;
                float* r1 = outN + (size_t)(cob + 1) * PIX;
                r0[pix]     = acc[mf][nf][0] + bv[nf][0];
                r1[pix]     = acc[mf][nf][1] + bv[nf][1];
                r0[pix + 8] = acc[mf][nf][2] + bv[nf][0];
                r1[pix + 8] = acc[mf][nf][3] + bv[nf][1];
            }
        }
    }
}

// ---------------------------------------------------------------------------
extern "C" void kernel_launch(void* const* d_in, const int* in_sizes, int n_in,
                              void* d_out, int out_size) {
    const float* x    = (const float*)d_in[0];
    const float* w    = (const float*)d_in[1];
    const float* bias = (const float*)d_in[2];
    float* out        = (float*)d_out;

    void *pxq, *pxt, *pwq, *pwk;
    cudaGetSymbolAddress(&pxq, g_xq);
    cudaGetSymbolAddress(&pxt, g_xt);
    cudaGetSymbolAddress(&pwq, g_wq);
    cudaGetSymbolAddress(&pwk, g_wk);
    __nv_bfloat16* xq = (__nv_bfloat16*)pxq;
    __nv_bfloat16* xt = (__nv_bfloat16*)pxt;
    __nv_bfloat16* wq = (__nv_bfloat16*)pwq;
    __nv_bfloat16* wk = (__nv_bfloat16*)pwk;

    const int n4x = NX / 4;          // 6,422,528
    const int n4w = NWELEM / 4;      // 9,216
    bfp_quant_kernel<<<(n4x + 2303) / 2304, 256>>>((const float4*)x, n4x, (uint2*)xq);
    bfp_quant_kernel<<<(n4w + 2303) / 2304, 256>>>((const float4*)w, n4w, (uint2*)wq);
    transpose_kernel<<<dim3(PIX / 64, N_BATCH), 256>>>(xq, xt);
    repack_w_kernel<<<(9 * 64 * 64 + 255) / 256, 256>>>(wq, wk);

    cudaFuncSetAttribute(conv_mma_kernel,
                         cudaFuncAttributeMaxDynamicSharedMemorySize,
                         CONV_SMEM);
    conv_mma_kernel<<<148, 512, CONV_SMEM>>>(xt, wk, bias, out);
}